// round 1
// baseline (speedup 1.0000x reference)
#include <cuda_runtime.h>
#include <math.h>

#define B_SZ   65536
#define BLK    512
#define CU_N   256
#define TAPS   100

// ---------------- scratch (no cudaMalloc allowed) ----------------
__device__ float g_h [(size_t)B_SZ * BLK];   // encoder hidden (post-PReLU)
__device__ float g_d [(size_t)B_SZ * BLK];   // decoder hidden (post-PReLU)
__device__ float g_y [(size_t)B_SZ * CU_N];  // channel symbols
__device__ float g_ps [256 * 512];
__device__ float g_pss[256 * 512];
__device__ float g_scale[512];
__device__ float g_shift[512];
__device__ float g_beff [512];
__device__ float g_nc  [CU_N];

// ---------------- FIR on noise (mode='same'), writes output tail too --------
__global__ void conv_noise(const float* __restrict__ noise,
                           const float* __restrict__ fir,
                           float* __restrict__ nc,
                           float* __restrict__ out_tail)
{
    __shared__ float sn[CU_N];
    __shared__ float sf[TAPS];
    int t = threadIdx.x;                       // 256 threads
    double snr = pow(10.0, 0.7);               // SNR_DB=7 -> 10^0.7
    float  ns  = (float)sqrt(1.0 / (4.0 * snr));  // rate = 512/256 = 2
    sn[t] = noise[t] * ns;
    if (t < TAPS) sf[t] = fir[t];
    __syncthreads();
    float s = 0.f;
    #pragma unroll 4
    for (int i = 0; i < TAPS; ++i) {
        int k = t + 49 - i;                    // 'same' offset = (TAPS-1)//2
        if (k >= 0 && k < CU_N) s += sf[i] * sn[k];
    }
    nc[t] = s;
    out_tail[t] = s;
}

// ---------------- column stats: partial (256 blocks x 512 threads) ----------
__global__ void stats_partial(const float* __restrict__ H,
                              float* __restrict__ ps, float* __restrict__ pss)
{
    int col = threadIdx.x;                     // 512
    size_t base = (size_t)blockIdx.x * 256 * 512 + col;
    float s = 0.f, ss = 0.f;
    #pragma unroll 4
    for (int r = 0; r < 256; ++r) {
        float v = H[base + (size_t)r * 512];
        s += v; ss = fmaf(v, v, ss);
    }
    ps [blockIdx.x * 512 + col] = s;
    pss[blockIdx.x * 512 + col] = ss;
}

// ---------------- finalize: scale = g*rsqrt(var+eps), shift = bt - mu*scale -
__global__ void stats_final(const float* __restrict__ ps, const float* __restrict__ pss,
                            const float* __restrict__ g,  const float* __restrict__ bt,
                            float* __restrict__ scale, float* __restrict__ shift)
{
    int col = threadIdx.x;                     // 512 threads, 1 block
    float s = 0.f, ss = 0.f;
    for (int b = 0; b < 256; ++b) {
        s  += ps [b * 512 + col];
        ss += pss[b * 512 + col];
    }
    float mean = s * (1.0f / 65536.0f);
    float var  = fmaf(-mean, mean, ss * (1.0f / 65536.0f));
    float sc   = g[col] * rsqrtf(var + 1e-5f);
    scale[col] = sc;
    shift[col] = fmaf(-mean, sc, bt[col]);
}

// ---------------- bias fold: out[j] = b[j] + dot(Wrow_j, vec) ----------------
__global__ void fold_bias(const float* __restrict__ Wm, const float* __restrict__ b,
                          const float* __restrict__ vec, float* __restrict__ out, int K)
{
    int j = blockIdx.x;
    float s = 0.f;
    for (int k = threadIdx.x; k < K; k += blockDim.x)
        s = fmaf(Wm[(size_t)j * K + k], vec[k], s);
    #pragma unroll
    for (int o = 16; o; o >>= 1) s += __shfl_xor_sync(0xffffffffu, s, o);
    __shared__ float red[4];
    if ((threadIdx.x & 31) == 0) red[threadIdx.x >> 5] = s;
    __syncthreads();
    if (threadIdx.x == 0) {
        float t = red[0] + red[1] + red[2] + red[3];
        out[j] = b[j] + t;
    }
}

// ---------------- per-row L2 normalize: y *= sqrt(CU)/||y|| ------------------
__global__ void rownorm(float* __restrict__ Y)
{
    int warp = threadIdx.x >> 5, lane = threadIdx.x & 31;   // 8 warps/block
    size_t row = (size_t)blockIdx.x * 8 + warp;
    float4* p = reinterpret_cast<float4*>(Y + row * CU_N);  // 64 float4/row
    float4 v0 = p[lane];
    float4 v1 = p[lane + 32];
    float ss = v0.x*v0.x + v0.y*v0.y + v0.z*v0.z + v0.w*v0.w
             + v1.x*v1.x + v1.y*v1.y + v1.z*v1.z + v1.w*v1.w;
    #pragma unroll
    for (int o = 16; o; o >>= 1) ss += __shfl_xor_sync(0xffffffffu, ss, o);
    float s = 16.0f * rsqrtf(ss);               // sqrt(256)=16
    v0.x*=s; v0.y*=s; v0.z*=s; v0.w*=s;
    v1.x*=s; v1.y*=s; v1.z*=s; v1.w*=s;
    p[lane] = v0; p[lane + 32] = v1;
}

// ---------------- C[M,N] = act( A[M,K] @ (W*scale_k)^T + bias ) --------------
// 128x128x16 tile, 256 threads, 8x8 per thread.
template<bool USE_SCALE, bool USE_PRELU>
__global__ __launch_bounds__(256, 2)
void gemm_kernel(const float* __restrict__ A, const float* __restrict__ W,
                 const float* __restrict__ bias, const float* __restrict__ wscale,
                 const float* __restrict__ aprelu, float* __restrict__ C,
                 int K, int N)
{
    const int BK = 16;
    __shared__ float As[BK][128];
    __shared__ float Ws[BK][128];
    int tid = threadIdx.x;
    int tx = tid & 15, ty = tid >> 4;
    size_t m0 = (size_t)blockIdx.y * 128;
    int    n0 = blockIdx.x * 128;

    float acc[8][8];
    #pragma unroll
    for (int i = 0; i < 8; ++i)
        #pragma unroll
        for (int j = 0; j < 8; ++j) acc[i][j] = 0.f;

    const float* Ap = A + m0 * K;
    const float* Wp = W + (size_t)n0 * K;

    int r0 = tid >> 2;            // 0..63
    int c0 = (tid & 3) * 4;       // 0,4,8,12

    for (int k0 = 0; k0 < K; k0 += BK) {
        #pragma unroll
        for (int it = 0; it < 2; ++it) {
            int r = r0 + it * 64;
            float4 va = *reinterpret_cast<const float4*>(Ap + (size_t)r * K + k0 + c0);
            As[c0+0][r] = va.x; As[c0+1][r] = va.y; As[c0+2][r] = va.z; As[c0+3][r] = va.w;
            float4 vw = *reinterpret_cast<const float4*>(Wp + (size_t)r * K + k0 + c0);
            if (USE_SCALE) {
                vw.x *= wscale[k0+c0+0]; vw.y *= wscale[k0+c0+1];
                vw.z *= wscale[k0+c0+2]; vw.w *= wscale[k0+c0+3];
            }
            Ws[c0+0][r] = vw.x; Ws[c0+1][r] = vw.y; Ws[c0+2][r] = vw.z; Ws[c0+3][r] = vw.w;
        }
        __syncthreads();
        #pragma unroll
        for (int kk = 0; kk < BK; ++kk) {
            float4 a0 = *reinterpret_cast<const float4*>(&As[kk][ty * 8]);
            float4 a1 = *reinterpret_cast<const float4*>(&As[kk][ty * 8 + 4]);
            float4 b0 = *reinterpret_cast<const float4*>(&Ws[kk][tx * 8]);
            float4 b1 = *reinterpret_cast<const float4*>(&Ws[kk][tx * 8 + 4]);
            float av[8] = {a0.x,a0.y,a0.z,a0.w,a1.x,a1.y,a1.z,a1.w};
            float bv[8] = {b0.x,b0.y,b0.z,b0.w,b1.x,b1.y,b1.z,b1.w};
            #pragma unroll
            for (int i = 0; i < 8; ++i)
                #pragma unroll
                for (int j = 0; j < 8; ++j)
                    acc[i][j] = fmaf(av[i], bv[j], acc[i][j]);
        }
        __syncthreads();
    }

    float ap = USE_PRELU ? *aprelu : 0.f;
    float bcol[8];
    #pragma unroll
    for (int j = 0; j < 8; ++j) bcol[j] = bias[n0 + tx * 8 + j];
    #pragma unroll
    for (int i = 0; i < 8; ++i) {
        size_t row = m0 + ty * 8 + i;
        float* Cp = C + row * N + n0 + tx * 8;
        float v[8];
        #pragma unroll
        for (int j = 0; j < 8; ++j) {
            float o = acc[i][j] + bcol[j];
            if (USE_PRELU) o = (o > 0.f) ? o : ap * o;
            v[j] = o;
        }
        *reinterpret_cast<float4*>(Cp)     = make_float4(v[0], v[1], v[2], v[3]);
        *reinterpret_cast<float4*>(Cp + 4) = make_float4(v[4], v[5], v[6], v[7]);
    }
}

// ---------------------------------------------------------------------------
extern "C" void kernel_launch(void* const* d_in, const int* in_sizes, int n_in,
                              void* d_out, int out_size)
{
    const float* x    = (const float*)d_in[0];
    const float* noise= (const float*)d_in[1];
    const float* W1   = (const float*)d_in[2];
    const float* b1   = (const float*)d_in[3];
    const float* a1   = (const float*)d_in[4];
    const float* g1v  = (const float*)d_in[5];
    const float* bt1  = (const float*)d_in[6];
    const float* W2   = (const float*)d_in[7];
    const float* b2   = (const float*)d_in[8];
    const float* W3   = (const float*)d_in[9];
    const float* b3   = (const float*)d_in[10];
    const float* a2   = (const float*)d_in[11];
    const float* g2v  = (const float*)d_in[12];
    const float* bt2  = (const float*)d_in[13];
    const float* W4   = (const float*)d_in[14];
    const float* b4   = (const float*)d_in[15];
    const float* fir  = (const float*)d_in[16];
    float* out = (float*)d_out;

    float *h, *d, *y, *ps, *pss, *scale, *shift, *beff, *nc;
    cudaGetSymbolAddress((void**)&h,     g_h);
    cudaGetSymbolAddress((void**)&d,     g_d);
    cudaGetSymbolAddress((void**)&y,     g_y);
    cudaGetSymbolAddress((void**)&ps,    g_ps);
    cudaGetSymbolAddress((void**)&pss,   g_pss);
    cudaGetSymbolAddress((void**)&scale, g_scale);
    cudaGetSymbolAddress((void**)&shift, g_shift);
    cudaGetSymbolAddress((void**)&beff,  g_beff);
    cudaGetSymbolAddress((void**)&nc,    g_nc);

    const dim3 grid_n512(BLK / 128, B_SZ / 128);   // (4, 512)
    const dim3 grid_n256(CU_N / 128, B_SZ / 128);  // (2, 512)

    // 1) noise FIR (also writes noise_clipped to the output tail)
    conv_noise<<<1, 256>>>(noise, fir, nc, out + (size_t)B_SZ * BLK);

    // 2) h = prelu(x @ W1^T + b1)
    gemm_kernel<false, true><<<grid_n512, 256>>>(x, W1, b1, nullptr, a1, h, 512, 512);

    // 3) BN1 stats -> scale/shift
    stats_partial<<<256, 512>>>(h, ps, pss);
    stats_final<<<1, 512>>>(ps, pss, g1v, bt1, scale, shift);

    // 4) b2' = b2 + W2 @ shift ; y = h @ (W2*scale)^T + b2'
    fold_bias<<<CU_N, 128>>>(W2, b2, shift, beff, 512);
    gemm_kernel<true, false><<<grid_n256, 256>>>(h, W2, beff, scale, nullptr, y, 512, 256);

    // 5) row L2 normalize y (in place)
    rownorm<<<B_SZ / 8, 256>>>(y);

    // 6) b3' = b3 + W3 @ noise_clipped ; d = prelu(y @ W3^T + b3')
    fold_bias<<<BLK, 128>>>(W3, b3, nc, beff, 256);
    gemm_kernel<false, true><<<grid_n512, 256>>>(y, W3, beff, nullptr, a2, d, 256, 512);

    // 7) BN2 stats -> scale/shift
    stats_partial<<<256, 512>>>(d, ps, pss);
    stats_final<<<1, 512>>>(ps, pss, g2v, bt2, scale, shift);

    // 8) b4' = b4 + W4 @ shift ; out = d @ (W4*scale)^T + b4'
    fold_bias<<<BLK, 128>>>(W4, b4, shift, beff, 512);
    gemm_kernel<true, false><<<grid_n512, 256>>>(d, W4, beff, scale, nullptr, out, 512, 512);
}

// round 6
// speedup vs baseline: 3.7901x; 3.7901x over previous
#include <cuda_runtime.h>
#include <cuda_bf16.h>
#include <cstdint>
#include <math.h>

#define B_SZ   65536
#define BLK    512
#define CU_N   256
#define TAPS   100

typedef __nv_bfloat16 bf16;

// tcgen05 only exists on the arch-specific target (sm_103a). The compute_103
// virtual pass compiles a correct SIMT fallback instead (never executed at
// runtime — the sm_103a cubin is preferred).
#if defined(__CUDA_ARCH__) && defined(__CUDA_ARCH_FEAT_SM103_ALL)
#define TC_OK 1
#else
#define TC_OK 0
#endif

// ------------------------- scratch (__device__ globals; no cudaMalloc) -----
__device__ __align__(1024) bf16 g_xh[(size_t)B_SZ * BLK];
__device__ __align__(1024) bf16 g_xl[(size_t)B_SZ * BLK];
__device__ __align__(1024) bf16 g_hh[(size_t)B_SZ * BLK];
__device__ __align__(1024) bf16 g_hl[(size_t)B_SZ * BLK];
__device__ __align__(1024) bf16 g_yh[(size_t)B_SZ * CU_N];
__device__ __align__(1024) bf16 g_yl[(size_t)B_SZ * CU_N];
__device__ __align__(1024) bf16 g_dh[(size_t)B_SZ * BLK];
__device__ __align__(1024) bf16 g_dl[(size_t)B_SZ * BLK];
__device__ __align__(1024) bf16 g_W1h[512*512], g_W1l[512*512];
__device__ __align__(1024) bf16 g_W2h[256*512], g_W2l[256*512];
__device__ __align__(1024) bf16 g_W3h[512*256], g_W3l[512*256];
__device__ __align__(1024) bf16 g_W4h[512*512], g_W4l[512*512];
__device__ float g_ps [256*512];
__device__ float g_pss[256*512];
__device__ float g_scale[512];
__device__ float g_shift[512];
__device__ float g_beff [512];
__device__ float g_nc  [CU_N];

// ------------------------- common helpers ----------------------------------
__device__ __forceinline__ float2 bf2_to_f2(uint32_t u) {
    __nv_bfloat162 t = *reinterpret_cast<__nv_bfloat162*>(&u);
    return __bfloat1622float2(t);
}
__device__ __forceinline__ uint32_t f2_to_bf2(float a, float b) {
    __nv_bfloat162 t = __floats2bfloat162_rn(a, b);
    return *reinterpret_cast<uint32_t*>(&t);
}
__device__ __forceinline__ void split1(float v, float& hi, float& lo) {
    bf16 h = __float2bfloat16(v);
    hi = __bfloat162float(h);
    lo = v - hi;
}

#if TC_OK
// ------------------------- sm_103a PTX helpers ------------------------------
__device__ __forceinline__ uint32_t smem_u32(const void* p) {
    uint32_t a;
    asm("{ .reg .u64 t; cvta.to.shared.u64 t, %1; cvt.u32.u64 %0, t; }"
        : "=r"(a) : "l"(p));
    return a;
}

__device__ __forceinline__ uint32_t elect1() {
    uint32_t p;
    asm volatile("{\n\t.reg .pred P;\n\telect.sync _|P, 0xFFFFFFFF;\n\t"
                 "selp.b32 %0, 1, 0, P;\n\t}" : "=r"(p));
    return p;
}

#define TCGEN05_ALLOC(smem_addr, nCols) \
    asm volatile("tcgen05.alloc.cta_group::1.sync.aligned.shared::cta.b32 [%0], %1;" \
                 :: "r"((uint32_t)(smem_addr)), "r"((uint32_t)(nCols)) : "memory")
#define TCGEN05_DEALLOC(tmem_addr, nCols) \
    asm volatile("tcgen05.dealloc.cta_group::1.sync.aligned.b32 %0, %1;" \
                 :: "r"(tmem_addr), "r"((uint32_t)(nCols)))
#define TCGEN05_RELINQUISH() \
    asm volatile("tcgen05.relinquish_alloc_permit.cta_group::1.sync.aligned;")
#define TCGEN05_COMMIT(mbar) \
    asm volatile("tcgen05.commit.cta_group::1.mbarrier::arrive::one.shared::cluster.b64 [%0];" \
                 :: "r"((uint32_t)(mbar)) : "memory")
#define TCGEN05_FENCE_AFTER() \
    asm volatile("tcgen05.fence::after_thread_sync;" ::: "memory")
#define TCGEN05_FENCE_BEFORE() \
    asm volatile("tcgen05.fence::before_thread_sync;" ::: "memory")
#define TCGEN05_WAIT_LD() \
    asm volatile("tcgen05.wait::ld.sync.aligned;" ::: "memory")
#define MBARRIER_INIT(mbar, cnt) \
    asm volatile("mbarrier.init.shared.b64 [%0], %1;" \
                 :: "r"((uint32_t)(mbar)), "r"((uint32_t)(cnt)) : "memory")
#define FENCE_PROXY_ASYNC() \
    asm volatile("fence.proxy.async.shared::cta;" ::: "memory")

#define MBARRIER_WAIT_PARITY(mbar_smem_addr, phase_parity) do { \
    uint32_t _mbar = (uint32_t)(mbar_smem_addr); \
    uint32_t _parity = (uint32_t)(phase_parity); \
    uint32_t _done; \
    asm volatile("{\n\t.reg .pred p;\n\t" \
        "mbarrier.try_wait.parity.acquire.cta.shared::cta.b64 p, [%1], %2;\n\t" \
        "selp.b32 %0, 1, 0, p;\n\t}" \
        : "=r"(_done) : "r"(_mbar), "r"(_parity) : "memory"); \
    if (!_done) { \
        asm volatile("{\n\t.reg .pred P1;\n\t" \
            "WAIT_LOOP_%=:\n\t" \
            "mbarrier.try_wait.parity.acquire.cta.shared::cta.b64 P1, [%0], %1, 0x989680;\n\t" \
            "@P1 bra.uni WAIT_DONE_%=;\n\t" \
            "bra.uni WAIT_LOOP_%=;\n\t" \
            "WAIT_DONE_%=:\n\t}" \
            :: "r"(_mbar), "r"(_parity) : "memory"); \
    } \
} while (0)

#define TCGEN05_LD_32X32B_X32(r, tmem_addr) \
    asm volatile("tcgen05.ld.sync.aligned.32x32b.x32.b32 " \
        "{%0, %1, %2, %3, %4, %5, %6, %7, " \
        " %8, %9, %10, %11, %12, %13, %14, %15, " \
        " %16, %17, %18, %19, %20, %21, %22, %23, " \
        " %24, %25, %26, %27, %28, %29, %30, %31}, [%32];" \
        : "=r"((r)[0]),  "=r"((r)[1]),  "=r"((r)[2]),  "=r"((r)[3]), \
          "=r"((r)[4]),  "=r"((r)[5]),  "=r"((r)[6]),  "=r"((r)[7]), \
          "=r"((r)[8]),  "=r"((r)[9]),  "=r"((r)[10]), "=r"((r)[11]), \
          "=r"((r)[12]), "=r"((r)[13]), "=r"((r)[14]), "=r"((r)[15]), \
          "=r"((r)[16]), "=r"((r)[17]), "=r"((r)[18]), "=r"((r)[19]), \
          "=r"((r)[20]), "=r"((r)[21]), "=r"((r)[22]), "=r"((r)[23]), \
          "=r"((r)[24]), "=r"((r)[25]), "=r"((r)[26]), "=r"((r)[27]), \
          "=r"((r)[28]), "=r"((r)[29]), "=r"((r)[30]), "=r"((r)[31]) \
        : "r"(tmem_addr))

// 64-bit SMEM descriptor, SW128 K-major (LBO=1, SBO=64, version=1)
static __device__ __forceinline__ uint64_t make_desc_sw128(uint32_t base) {
    const uint64_t BASE =
        (uint64_t(2)  << 61) | (uint64_t(1) << 46) |
        (uint64_t(64) << 32) | (uint64_t(1) << 16);
    return BASE | ((uint64_t)(base >> 4) & 0x3FFF);
}

// bf16 SS-mode MMA, cta_group::1, D fp32
__device__ __forceinline__ void mma_f16_ss(uint32_t d, uint64_t ad, uint64_t bd,
                                           uint32_t idesc, uint32_t en) {
    asm volatile("{\n\t.reg .pred p;\n\tsetp.ne.u32 p, %5, 0;\n\t"
        "tcgen05.mma.cta_group::1.kind::f16 [%0], %1, %2, %3, {%4, %4, %4, %4}, p;\n\t}"
        :: "r"(d), "l"(ad), "l"(bd), "r"(idesc), "r"(0u), "r"(en) : "memory");
}
#endif // TC_OK

// ------------------------- FIR on noise ------------------------------------
__global__ void conv_noise(const float* __restrict__ noise,
                           const float* __restrict__ fir,
                           float* __restrict__ nc,
                           float* __restrict__ out_tail)
{
    __shared__ float sn[CU_N];
    __shared__ float sf[TAPS];
    int t = threadIdx.x;
    double snr = pow(10.0, 0.7);
    float  ns  = (float)sqrt(1.0 / (4.0 * snr));
    sn[t] = noise[t] * ns;
    if (t < TAPS) sf[t] = fir[t];
    __syncthreads();
    float s = 0.f;
    #pragma unroll 4
    for (int i = 0; i < TAPS; ++i) {
        int k = t + 49 - i;
        if (k >= 0 && k < CU_N) s += sf[i] * sn[k];
    }
    nc[t] = s;
    out_tail[t] = s;
}

// ------------------------- split fp32 tensor -> bf16 hi/lo ------------------
__global__ void split_f32(const float* __restrict__ X,
                          bf16* __restrict__ H, bf16* __restrict__ L)
{
    size_t i = ((size_t)blockIdx.x * blockDim.x + threadIdx.x) * 8;
    float4 v0 = *reinterpret_cast<const float4*>(X + i);
    float4 v1 = *reinterpret_cast<const float4*>(X + i + 4);
    float h[8], l[8];
    float vv[8] = {v0.x, v0.y, v0.z, v0.w, v1.x, v1.y, v1.z, v1.w};
    #pragma unroll
    for (int j = 0; j < 8; ++j) split1(vv[j], h[j], l[j]);
    uint4 uh = make_uint4(f2_to_bf2(h[0],h[1]), f2_to_bf2(h[2],h[3]),
                          f2_to_bf2(h[4],h[5]), f2_to_bf2(h[6],h[7]));
    uint4 ul = make_uint4(f2_to_bf2(l[0],l[1]), f2_to_bf2(l[2],l[3]),
                          f2_to_bf2(l[4],l[5]), f2_to_bf2(l[6],l[7]));
    *reinterpret_cast<uint4*>(H + i) = uh;
    *reinterpret_cast<uint4*>(L + i) = ul;
}

// ------------------------- split weights (optional per-k scale) -------------
__global__ void split_w(const float* __restrict__ W, const float* __restrict__ scale,
                        bf16* __restrict__ Wh, bf16* __restrict__ Wl, int kmask)
{
    int i = blockIdx.x * blockDim.x + threadIdx.x;
    float v = W[i];
    if (scale) v *= scale[i & kmask];
    float h, l;
    split1(v, h, l);
    Wh[i] = __float2bfloat16(h);
    Wl[i] = __float2bfloat16(l);
}

// ------------------------- column stats over bf16 hi/lo ---------------------
__global__ void stats_partial_bf(const bf16* __restrict__ Hh, const bf16* __restrict__ Hl,
                                 float* __restrict__ ps, float* __restrict__ pss)
{
    int col = threadIdx.x;                     // 512
    size_t base = (size_t)blockIdx.x * 256 * 512 + col;
    float s = 0.f, ss = 0.f;
    #pragma unroll 4
    for (int r = 0; r < 256; ++r) {
        size_t idx = base + (size_t)r * 512;
        float v = __bfloat162float(Hh[idx]) + __bfloat162float(Hl[idx]);
        s += v; ss = fmaf(v, v, ss);
    }
    ps [blockIdx.x * 512 + col] = s;
    pss[blockIdx.x * 512 + col] = ss;
}

__global__ void stats_final(const float* __restrict__ ps, const float* __restrict__ pss,
                            const float* __restrict__ g,  const float* __restrict__ bt,
                            float* __restrict__ scale, float* __restrict__ shift)
{
    int col = threadIdx.x;
    float s = 0.f, ss = 0.f;
    for (int b = 0; b < 256; ++b) {
        s  += ps [b * 512 + col];
        ss += pss[b * 512 + col];
    }
    float mean = s * (1.0f / 65536.0f);
    float var  = fmaf(-mean, mean, ss * (1.0f / 65536.0f));
    float sc   = g[col] * rsqrtf(var + 1e-5f);
    scale[col] = sc;
    shift[col] = fmaf(-mean, sc, bt[col]);
}

// ------------------------- bias fold ----------------------------------------
__global__ void fold_bias(const float* __restrict__ Wm, const float* __restrict__ b,
                          const float* __restrict__ vec, float* __restrict__ out, int K)
{
    int j = blockIdx.x;
    float s = 0.f;
    for (int k = threadIdx.x; k < K; k += blockDim.x)
        s = fmaf(Wm[(size_t)j * K + k], vec[k], s);
    #pragma unroll
    for (int o = 16; o; o >>= 1) s += __shfl_xor_sync(0xffffffffu, s, o);
    __shared__ float red[4];
    if ((threadIdx.x & 31) == 0) red[threadIdx.x >> 5] = s;
    __syncthreads();
    if (threadIdx.x == 0) out[j] = b[j] + red[0] + red[1] + red[2] + red[3];
}

// ------------------------- row L2 normalize on hi/lo ------------------------
__global__ void rownorm_bf(bf16* __restrict__ Yh, bf16* __restrict__ Yl)
{
    int wid = threadIdx.x >> 5, lane = threadIdx.x & 31;  // 8 warps
    size_t row = (size_t)blockIdx.x * 8 + wid;
    uint4* ph = reinterpret_cast<uint4*>(Yh + row * CU_N); // 32 uint4 / row
    uint4* pl = reinterpret_cast<uint4*>(Yl + row * CU_N);
    uint4 uh = ph[lane], ul = pl[lane];
    uint32_t hw[4] = {uh.x, uh.y, uh.z, uh.w};
    uint32_t lw[4] = {ul.x, ul.y, ul.z, ul.w};
    float v[8];
    #pragma unroll
    for (int q = 0; q < 4; ++q) {
        float2 a = bf2_to_f2(hw[q]);
        float2 b = bf2_to_f2(lw[q]);
        v[2*q]   = a.x + b.x;
        v[2*q+1] = a.y + b.y;
    }
    float ss = 0.f;
    #pragma unroll
    for (int q = 0; q < 8; ++q) ss = fmaf(v[q], v[q], ss);
    #pragma unroll
    for (int o = 16; o; o >>= 1) ss += __shfl_xor_sync(0xffffffffu, ss, o);
    float s = 16.0f * rsqrtf(ss);
    float h[8], l[8];
    #pragma unroll
    for (int q = 0; q < 8; ++q) split1(s * v[q], h[q], l[q]);
    uh = make_uint4(f2_to_bf2(h[0],h[1]), f2_to_bf2(h[2],h[3]),
                    f2_to_bf2(h[4],h[5]), f2_to_bf2(h[6],h[7]));
    ul = make_uint4(f2_to_bf2(l[0],l[1]), f2_to_bf2(l[2],l[3]),
                    f2_to_bf2(l[4],l[5]), f2_to_bf2(l[6],l[7]));
    ph[lane] = uh;
    pl[lane] = ul;
}

// ------------------------- tcgen05 GEMM -------------------------------------
// D[128 x 256] tile. C = act( (Ah+Al)[M,K] @ ((Wh+Wl)[N,K])^T + bias )
// 3-term bf16 emulation: Ah*Wh + Ah*Wl + Al*Wh, fp32 accum in TMEM.
#define STAGE_BYTES  (96*1024)
#define SMEM_TOTAL_G (1024 + 2*STAGE_BYTES)
#define EPI_LD 264

template<int K, bool PRELU, bool SPLIT_OUT>
__global__ void __launch_bounds__(256, 1)
tc_gemm(const bf16* __restrict__ Ah, const bf16* __restrict__ Al,
        const bf16* __restrict__ Wh, const bf16* __restrict__ Wl,
        const float* __restrict__ bias, const float* __restrict__ aprelu,
        bf16* __restrict__ Oh, bf16* __restrict__ Ol, float* __restrict__ Of,
        int ldo)
{
#if TC_OK
    constexpr int NK = K / 64;
    constexpr uint32_t IDESC =
        (1u << 4) | (1u << 7) | (1u << 10) |        // F32 accum, BF16 a/b
        ((256u / 8) << 17) | ((128u / 16) << 24);   // N=256, M=128
    extern __shared__ __align__(1024) char sm[];
    const uint32_t sbase = smem_u32(sm);
    const int tid = threadIdx.x, wid = tid >> 5, lane = tid & 31;
    const size_t m0 = (size_t)blockIdx.y * 128;
    const size_t n0 = (size_t)blockIdx.x * 256;

    if (wid == 0) TCGEN05_ALLOC(sbase + 0, 256);
    if (tid == 0) { MBARRIER_INIT(sbase + 16, 1); MBARRIER_INIT(sbase + 24, 1); }
    FENCE_PROXY_ASYNC();
    __syncthreads();
    uint32_t tmem;
    asm volatile("ld.shared.b32 %0, [%1];" : "=r"(tmem) : "r"(sbase + 0));

    int ph0 = 0, ph1 = 0;
    #pragma unroll 1
    for (int kc = 0; kc < NK; ++kc) {
        const int s = kc & 1;
        char* stp = sm + 1024 + s * STAGE_BYTES;
        const uint32_t stb = sbase + 1024 + s * STAGE_BYTES;
        if (kc >= 2) {
            if (s == 0) { MBARRIER_WAIT_PARITY(sbase + 16, ph0); ph0 ^= 1; }
            else        { MBARRIER_WAIT_PARITY(sbase + 24, ph1); ph1 ^= 1; }
        }
        // A tiles: 128 rows x 64 bf16 (128B rows, SW128); hi then lo
        #pragma unroll
        for (int i = 0; i < 4; ++i) {
            int idx = tid + i * 256;
            int r = idx >> 3, c = idx & 7;
            size_t g = (m0 + r) * (size_t)K + (size_t)kc * 64 + c * 8;
            uint32_t b = r * 128 + c * 16;
            uint32_t sw = b ^ ((b >> 3) & 0x70);
            *reinterpret_cast<uint4*>(stp + sw)         = *reinterpret_cast<const uint4*>(Ah + g);
            *reinterpret_cast<uint4*>(stp + 16384 + sw) = *reinterpret_cast<const uint4*>(Al + g);
        }
        // W tiles: 256 rows x 64 bf16; hi then lo
        #pragma unroll
        for (int i = 0; i < 8; ++i) {
            int idx = tid + i * 256;
            int r = idx >> 3, c = idx & 7;
            size_t g = (n0 + r) * (size_t)K + (size_t)kc * 64 + c * 8;
            uint32_t b = r * 128 + c * 16;
            uint32_t sw = b ^ ((b >> 3) & 0x70);
            *reinterpret_cast<uint4*>(stp + 32768 + sw) = *reinterpret_cast<const uint4*>(Wh + g);
            *reinterpret_cast<uint4*>(stp + 65536 + sw) = *reinterpret_cast<const uint4*>(Wl + g);
        }
        FENCE_PROXY_ASYNC();
        __syncthreads();
        if (wid == 0 && elect1()) {
            uint64_t dAh = make_desc_sw128(stb);
            uint64_t dAl = make_desc_sw128(stb + 16384);
            uint64_t dWh = make_desc_sw128(stb + 32768);
            uint64_t dWl = make_desc_sw128(stb + 65536);
            #pragma unroll
            for (int ks = 0; ks < 4; ++ks) {
                mma_f16_ss(tmem, dAh + ks*2, dWh + ks*2, IDESC, (kc == 0 && ks == 0) ? 0u : 1u);
                mma_f16_ss(tmem, dAh + ks*2, dWl + ks*2, IDESC, 1u);
                mma_f16_ss(tmem, dAl + ks*2, dWh + ks*2, IDESC, 1u);
            }
            TCGEN05_COMMIT(sbase + 16 + s * 8);
        }
    }
    // wait for the last commit (covers all outstanding MMAs)
    {
        const int s = (NK - 1) & 1;
        if (s == 0) { MBARRIER_WAIT_PARITY(sbase + 16, ph0); }
        else        { MBARRIER_WAIT_PARITY(sbase + 24, ph1); }
    }
    TCGEN05_FENCE_AFTER();

    // epilogue: LDTM -> bias (+prelu) -> (split hi/lo | f32) via SMEM transpose
    const float alpha = PRELU ? *aprelu : 0.f;
    const int rloc = (wid & 3) * 32 + lane;
    const int cb = (wid >> 2) * 128;
    bf16*  smH = reinterpret_cast<bf16*>(sm + 1024);
    bf16*  smL = smH + 128 * EPI_LD;
    float* smF = reinterpret_cast<float*>(sm + 1024);

    #pragma unroll 1
    for (int ch = 0; ch < 4; ++ch) {
        int c0 = cb + ch * 32;
        uint32_t r[32];
        TCGEN05_LD_32X32B_X32(r, tmem + c0);
        TCGEN05_WAIT_LD();
        #pragma unroll
        for (int j = 0; j < 32; ++j) {
            float o = __uint_as_float(r[j]) + bias[n0 + c0 + j];
            if (PRELU) o = (o > 0.f) ? o : alpha * o;
            if (SPLIT_OUT) {
                float h, l;
                split1(o, h, l);
                smH[rloc * EPI_LD + c0 + j] = __float2bfloat16(h);
                smL[rloc * EPI_LD + c0 + j] = __float2bfloat16(l);
            } else {
                smF[rloc * EPI_LD + c0 + j] = o;
            }
        }
    }
    TCGEN05_FENCE_BEFORE();
    __syncthreads();
    if (wid == 0) { TCGEN05_RELINQUISH(); TCGEN05_DEALLOC(tmem, 256); }

    if (SPLIT_OUT) {
        // 128 rows x 256 cols bf16 = 4096 uint4 per tensor, 32 uint4 per row
        #pragma unroll
        for (int i = 0; i < 16; ++i) {
            int idx = tid + i * 256;
            int r = idx >> 5, c = idx & 31;
            size_t g = (m0 + r) * (size_t)ldo + n0 + c * 8;
            *reinterpret_cast<uint4*>(Oh + g) =
                *reinterpret_cast<uint4*>(smH + r * EPI_LD + c * 8);
            *reinterpret_cast<uint4*>(Ol + g) =
                *reinterpret_cast<uint4*>(smL + r * EPI_LD + c * 8);
        }
    } else {
        // 128 rows x 256 cols f32 = 8192 uint4, 64 uint4 per row
        #pragma unroll
        for (int i = 0; i < 32; ++i) {
            int idx = tid + i * 256;
            int r = idx >> 6, c = idx & 63;
            size_t g = (m0 + r) * (size_t)ldo + n0 + c * 4;
            *reinterpret_cast<uint4*>(Of + g) =
                *reinterpret_cast<uint4*>(smF + r * EPI_LD + c * 4);
        }
    }
#else
    // --------- correct SIMT fallback (compute_103 virtual pass; not used) ---
    const int tid = threadIdx.x;
    const size_t m0 = (size_t)blockIdx.y * 128;
    const size_t n0 = (size_t)blockIdx.x * 256;
    const float alpha = PRELU ? *aprelu : 0.f;
    for (int o = tid; o < 128 * 256; o += 256) {
        int r = o >> 8, c = o & 255;
        float acc = 0.f;
        for (int k = 0; k < K; ++k) {
            float a = __bfloat162float(Ah[(m0 + r) * K + k]) +
                      __bfloat162float(Al[(m0 + r) * K + k]);
            float w = __bfloat162float(Wh[(n0 + c) * K + k]) +
                      __bfloat162float(Wl[(n0 + c) * K + k]);
            acc = fmaf(a, w, acc);
        }
        float v = acc + bias[n0 + c];
        if (PRELU) v = (v > 0.f) ? v : alpha * v;
        size_t g = (m0 + r) * (size_t)ldo + n0 + c;
        if (SPLIT_OUT) {
            float h, l;
            split1(v, h, l);
            Oh[g] = __float2bfloat16(h);
            Ol[g] = __float2bfloat16(l);
        } else {
            Of[g] = v;
        }
    }
#endif
}

// ---------------------------------------------------------------------------
extern "C" void kernel_launch(void* const* d_in, const int* in_sizes, int n_in,
                              void* d_out, int out_size)
{
    const float* x    = (const float*)d_in[0];
    const float* noise= (const float*)d_in[1];
    const float* W1   = (const float*)d_in[2];
    const float* b1   = (const float*)d_in[3];
    const float* a1   = (const float*)d_in[4];
    const float* g1v  = (const float*)d_in[5];
    const float* bt1  = (const float*)d_in[6];
    const float* W2   = (const float*)d_in[7];
    const float* b2   = (const float*)d_in[8];
    const float* W3   = (const float*)d_in[9];
    const float* b3   = (const float*)d_in[10];
    const float* a2   = (const float*)d_in[11];
    const float* g2v  = (const float*)d_in[12];
    const float* bt2  = (const float*)d_in[13];
    const float* W4   = (const float*)d_in[14];
    const float* b4   = (const float*)d_in[15];
    const float* fir  = (const float*)d_in[16];
    float* out = (float*)d_out;

    bf16 *xh,*xl,*hh,*hl,*yh,*yl,*dh,*dl;
    bf16 *w1h,*w1l,*w2h,*w2l,*w3h,*w3l,*w4h,*w4l;
    float *ps,*pss,*scale,*shift,*beff,*nc;
    cudaGetSymbolAddress((void**)&xh, g_xh);  cudaGetSymbolAddress((void**)&xl, g_xl);
    cudaGetSymbolAddress((void**)&hh, g_hh);  cudaGetSymbolAddress((void**)&hl, g_hl);
    cudaGetSymbolAddress((void**)&yh, g_yh);  cudaGetSymbolAddress((void**)&yl, g_yl);
    cudaGetSymbolAddress((void**)&dh, g_dh);  cudaGetSymbolAddress((void**)&dl, g_dl);
    cudaGetSymbolAddress((void**)&w1h, g_W1h); cudaGetSymbolAddress((void**)&w1l, g_W1l);
    cudaGetSymbolAddress((void**)&w2h, g_W2h); cudaGetSymbolAddress((void**)&w2l, g_W2l);
    cudaGetSymbolAddress((void**)&w3h, g_W3h); cudaGetSymbolAddress((void**)&w3l, g_W3l);
    cudaGetSymbolAddress((void**)&w4h, g_W4h); cudaGetSymbolAddress((void**)&w4l, g_W4l);
    cudaGetSymbolAddress((void**)&ps, g_ps);   cudaGetSymbolAddress((void**)&pss, g_pss);
    cudaGetSymbolAddress((void**)&scale, g_scale); cudaGetSymbolAddress((void**)&shift, g_shift);
    cudaGetSymbolAddress((void**)&beff, g_beff);   cudaGetSymbolAddress((void**)&nc, g_nc);

    cudaFuncSetAttribute(tc_gemm<512, true,  true >, cudaFuncAttributeMaxDynamicSharedMemorySize, SMEM_TOTAL_G);
    cudaFuncSetAttribute(tc_gemm<512, false, true >, cudaFuncAttributeMaxDynamicSharedMemorySize, SMEM_TOTAL_G);
    cudaFuncSetAttribute(tc_gemm<256, true,  true >, cudaFuncAttributeMaxDynamicSharedMemorySize, SMEM_TOTAL_G);
    cudaFuncSetAttribute(tc_gemm<512, false, false>, cudaFuncAttributeMaxDynamicSharedMemorySize, SMEM_TOTAL_G);

    // 1) noise FIR (also writes noise_clipped to output tail)
    conv_noise<<<1, 256>>>(noise, fir, nc, out + (size_t)B_SZ * BLK);

    // 2) split x and W1
    split_f32<<<(B_SZ * (size_t)BLK) / 8 / 256, 256>>>(x, xh, xl);
    split_w<<<512 * 512 / 256, 256>>>(W1, nullptr, w1h, w1l, 511);

    // 3) h = prelu(x @ W1^T + b1)  -> hi/lo
    tc_gemm<512, true, true><<<dim3(2, 512), 256, SMEM_TOTAL_G>>>(
        xh, xl, w1h, w1l, b1, a1, hh, hl, nullptr, 512);

    // 4) BN1 stats
    stats_partial_bf<<<256, 512>>>(hh, hl, ps, pss);
    stats_final<<<1, 512>>>(ps, pss, g1v, bt1, scale, shift);

    // 5) y = h @ (W2*scale)^T + (b2 + W2@shift)
    fold_bias<<<CU_N, 128>>>(W2, b2, shift, beff, 512);
    split_w<<<256 * 512 / 256, 256>>>(W2, scale, w2h, w2l, 511);
    tc_gemm<512, false, true><<<dim3(1, 512), 256, SMEM_TOTAL_G>>>(
        hh, hl, w2h, w2l, beff, nullptr, yh, yl, nullptr, 256);

    // 6) row L2 normalize y
    rownorm_bf<<<B_SZ / 8, 256>>>(yh, yl);

    // 7) d = prelu(y @ W3^T + (b3 + W3@nc))
    fold_bias<<<BLK, 128>>>(W3, b3, nc, beff, 256);
    split_w<<<512 * 256 / 256, 256>>>(W3, nullptr, w3h, w3l, 255);
    tc_gemm<256, true, true><<<dim3(2, 512), 256, SMEM_TOTAL_G>>>(
        yh, yl, w3h, w3l, beff, a2, dh, dl, nullptr, 512);

    // 8) BN2 stats
    stats_partial_bf<<<256, 512>>>(dh, dl, ps, pss);
    stats_final<<<1, 512>>>(ps, pss, g2v, bt2, scale, shift);

    // 9) out = d @ (W4*scale)^T + (b4 + W4@shift)   (fp32)
    fold_bias<<<BLK, 128>>>(W4, b4, shift, beff, 512);
    split_w<<<512 * 512 / 256, 256>>>(W4, scale, w4h, w4l, 511);
    tc_gemm<512, false, false><<<dim3(2, 512), 256, SMEM_TOTAL_G>>>(
        dh, dl, w4h, w4l, beff, nullptr, nullptr, nullptr, out, 512);
}

// round 7
// speedup vs baseline: 3.8096x; 1.0051x over previous
#include <cuda_runtime.h>
#include <cuda_bf16.h>
#include <cstdint>
#include <math.h>

#define B_SZ   65536
#define BLK    512
#define CU_N   256
#define TAPS   100

typedef __nv_bfloat16 bf16;

// tcgen05 only exists on the arch-specific target (sm_103a). The compute_103
// virtual pass compiles a correct SIMT fallback instead (never executed at
// runtime — the sm_103a cubin is preferred).
#if defined(__CUDA_ARCH__) && defined(__CUDA_ARCH_FEAT_SM103_ALL)
#define TC_OK 1
#else
#define TC_OK 0
#endif

// ------------------------- scratch (__device__ globals; no cudaMalloc) -----
__device__ __align__(1024) bf16 g_xh[(size_t)B_SZ * BLK];
__device__ __align__(1024) bf16 g_xl[(size_t)B_SZ * BLK];
__device__ __align__(1024) bf16 g_hh[(size_t)B_SZ * BLK];
__device__ __align__(1024) bf16 g_hl[(size_t)B_SZ * BLK];
__device__ __align__(1024) bf16 g_yh[(size_t)B_SZ * CU_N];
__device__ __align__(1024) bf16 g_yl[(size_t)B_SZ * CU_N];
__device__ __align__(1024) bf16 g_dh[(size_t)B_SZ * BLK];
__device__ __align__(1024) bf16 g_dl[(size_t)B_SZ * BLK];
__device__ __align__(1024) bf16 g_W1h[512*512], g_W1l[512*512];
__device__ __align__(1024) bf16 g_W2h[256*512], g_W2l[256*512];
__device__ __align__(1024) bf16 g_W3h[512*256], g_W3l[512*256];
__device__ __align__(1024) bf16 g_W4h[512*512], g_W4l[512*512];
__device__ float g_ps [256*512];
__device__ float g_pss[256*512];
__device__ float g_scale[512];
__device__ float g_shift[512];
__device__ float g_beff [512];
__device__ float g_nc  [CU_N];

// ------------------------- common helpers ----------------------------------
__device__ __forceinline__ float2 bf2_to_f2(uint32_t u) {
    __nv_bfloat162 t = *reinterpret_cast<__nv_bfloat162*>(&u);
    return __bfloat1622float2(t);
}
__device__ __forceinline__ uint32_t f2_to_bf2(float a, float b) {
    __nv_bfloat162 t = __floats2bfloat162_rn(a, b);
    return *reinterpret_cast<uint32_t*>(&t);
}
__device__ __forceinline__ void split1(float v, float& hi, float& lo) {
    bf16 h = __float2bfloat16(v);
    hi = __bfloat162float(h);
    lo = v - hi;
}

#if TC_OK
// ------------------------- sm_103a PTX helpers ------------------------------
__device__ __forceinline__ uint32_t smem_u32(const void* p) {
    uint32_t a;
    asm("{ .reg .u64 t; cvta.to.shared.u64 t, %1; cvt.u32.u64 %0, t; }"
        : "=r"(a) : "l"(p));
    return a;
}

__device__ __forceinline__ uint32_t elect1() {
    uint32_t p;
    asm volatile("{\n\t.reg .pred P;\n\telect.sync _|P, 0xFFFFFFFF;\n\t"
                 "selp.b32 %0, 1, 0, P;\n\t}" : "=r"(p));
    return p;
}

#define TCGEN05_ALLOC(smem_addr, nCols) \
    asm volatile("tcgen05.alloc.cta_group::1.sync.aligned.shared::cta.b32 [%0], %1;" \
                 :: "r"((uint32_t)(smem_addr)), "r"((uint32_t)(nCols)) : "memory")
#define TCGEN05_DEALLOC(tmem_addr, nCols) \
    asm volatile("tcgen05.dealloc.cta_group::1.sync.aligned.b32 %0, %1;" \
                 :: "r"(tmem_addr), "r"((uint32_t)(nCols)))
#define TCGEN05_RELINQUISH() \
    asm volatile("tcgen05.relinquish_alloc_permit.cta_group::1.sync.aligned;")
#define TCGEN05_COMMIT(mbar) \
    asm volatile("tcgen05.commit.cta_group::1.mbarrier::arrive::one.shared::cluster.b64 [%0];" \
                 :: "r"((uint32_t)(mbar)) : "memory")
#define TCGEN05_FENCE_AFTER() \
    asm volatile("tcgen05.fence::after_thread_sync;" ::: "memory")
#define TCGEN05_FENCE_BEFORE() \
    asm volatile("tcgen05.fence::before_thread_sync;" ::: "memory")
#define TCGEN05_WAIT_LD() \
    asm volatile("tcgen05.wait::ld.sync.aligned;" ::: "memory")
#define MBARRIER_INIT(mbar, cnt) \
    asm volatile("mbarrier.init.shared.b64 [%0], %1;" \
                 :: "r"((uint32_t)(mbar)), "r"((uint32_t)(cnt)) : "memory")
#define FENCE_PROXY_ASYNC() \
    asm volatile("fence.proxy.async.shared::cta;" ::: "memory")

#define MBARRIER_WAIT_PARITY(mbar_smem_addr, phase_parity) do { \
    uint32_t _mbar = (uint32_t)(mbar_smem_addr); \
    uint32_t _parity = (uint32_t)(phase_parity); \
    uint32_t _done; \
    asm volatile("{\n\t.reg .pred p;\n\t" \
        "mbarrier.try_wait.parity.acquire.cta.shared::cta.b64 p, [%1], %2;\n\t" \
        "selp.b32 %0, 1, 0, p;\n\t}" \
        : "=r"(_done) : "r"(_mbar), "r"(_parity) : "memory"); \
    if (!_done) { \
        asm volatile("{\n\t.reg .pred P1;\n\t" \
            "WAIT_LOOP_%=:\n\t" \
            "mbarrier.try_wait.parity.acquire.cta.shared::cta.b64 P1, [%0], %1, 0x989680;\n\t" \
            "@P1 bra.uni WAIT_DONE_%=;\n\t" \
            "bra.uni WAIT_LOOP_%=;\n\t" \
            "WAIT_DONE_%=:\n\t}" \
            :: "r"(_mbar), "r"(_parity) : "memory"); \
    } \
} while (0)

#define TCGEN05_LD_32X32B_X32(r, tmem_addr) \
    asm volatile("tcgen05.ld.sync.aligned.32x32b.x32.b32 " \
        "{%0, %1, %2, %3, %4, %5, %6, %7, " \
        " %8, %9, %10, %11, %12, %13, %14, %15, " \
        " %16, %17, %18, %19, %20, %21, %22, %23, " \
        " %24, %25, %26, %27, %28, %29, %30, %31}, [%32];" \
        : "=r"((r)[0]),  "=r"((r)[1]),  "=r"((r)[2]),  "=r"((r)[3]), \
          "=r"((r)[4]),  "=r"((r)[5]),  "=r"((r)[6]),  "=r"((r)[7]), \
          "=r"((r)[8]),  "=r"((r)[9]),  "=r"((r)[10]), "=r"((r)[11]), \
          "=r"((r)[12]), "=r"((r)[13]), "=r"((r)[14]), "=r"((r)[15]), \
          "=r"((r)[16]), "=r"((r)[17]), "=r"((r)[18]), "=r"((r)[19]), \
          "=r"((r)[20]), "=r"((r)[21]), "=r"((r)[22]), "=r"((r)[23]), \
          "=r"((r)[24]), "=r"((r)[25]), "=r"((r)[26]), "=r"((r)[27]), \
          "=r"((r)[28]), "=r"((r)[29]), "=r"((r)[30]), "=r"((r)[31]) \
        : "r"(tmem_addr))

// 64-bit SMEM descriptor, SW128 K-major (LBO=1, SBO=64, version=1)
static __device__ __forceinline__ uint64_t make_desc_sw128(uint32_t base) {
    const uint64_t BASE =
        (uint64_t(2)  << 61) | (uint64_t(1) << 46) |
        (uint64_t(64) << 32) | (uint64_t(1) << 16);
    return BASE | ((uint64_t)(base >> 4) & 0x3FFF);
}

// bf16 SS-mode MMA, cta_group::1, D fp32
__device__ __forceinline__ void mma_f16_ss(uint32_t d, uint64_t ad, uint64_t bd,
                                           uint32_t idesc, uint32_t en) {
    asm volatile("{\n\t.reg .pred p;\n\tsetp.ne.u32 p, %5, 0;\n\t"
        "tcgen05.mma.cta_group::1.kind::f16 [%0], %1, %2, %3, {%4, %4, %4, %4}, p;\n\t}"
        :: "r"(d), "l"(ad), "l"(bd), "r"(idesc), "r"(0u), "r"(en) : "memory");
}
#endif // TC_OK

// ------------------------- FIR on noise ------------------------------------
__global__ void conv_noise(const float* __restrict__ noise,
                           const float* __restrict__ fir,
                           float* __restrict__ nc,
                           float* __restrict__ out_tail)
{
    __shared__ float sn[CU_N];
    __shared__ float sf[TAPS];
    int t = threadIdx.x;
    double snr = pow(10.0, 0.7);
    float  ns  = (float)sqrt(1.0 / (4.0 * snr));
    sn[t] = noise[t] * ns;
    if (t < TAPS) sf[t] = fir[t];
    __syncthreads();
    float s = 0.f;
    #pragma unroll 4
    for (int i = 0; i < TAPS; ++i) {
        int k = t + 49 - i;
        if (k >= 0 && k < CU_N) s += sf[i] * sn[k];
    }
    nc[t] = s;
    out_tail[t] = s;
}

// ------------------------- split fp32 tensor -> bf16 hi/lo ------------------
__global__ void split_f32(const float* __restrict__ X,
                          bf16* __restrict__ H, bf16* __restrict__ L)
{
    size_t i = ((size_t)blockIdx.x * blockDim.x + threadIdx.x) * 8;
    float4 v0 = *reinterpret_cast<const float4*>(X + i);
    float4 v1 = *reinterpret_cast<const float4*>(X + i + 4);
    float h[8], l[8];
    float vv[8] = {v0.x, v0.y, v0.z, v0.w, v1.x, v1.y, v1.z, v1.w};
    #pragma unroll
    for (int j = 0; j < 8; ++j) split1(vv[j], h[j], l[j]);
    uint4 uh = make_uint4(f2_to_bf2(h[0],h[1]), f2_to_bf2(h[2],h[3]),
                          f2_to_bf2(h[4],h[5]), f2_to_bf2(h[6],h[7]));
    uint4 ul = make_uint4(f2_to_bf2(l[0],l[1]), f2_to_bf2(l[2],l[3]),
                          f2_to_bf2(l[4],l[5]), f2_to_bf2(l[6],l[7]));
    *reinterpret_cast<uint4*>(H + i) = uh;
    *reinterpret_cast<uint4*>(L + i) = ul;
}

// ------------------------- split weights (optional per-k scale) -------------
__global__ void split_w(const float* __restrict__ W, const float* __restrict__ scale,
                        bf16* __restrict__ Wh, bf16* __restrict__ Wl, int kmask)
{
    int i = blockIdx.x * blockDim.x + threadIdx.x;
    float v = W[i];
    if (scale) v *= scale[i & kmask];
    float h, l;
    split1(v, h, l);
    Wh[i] = __float2bfloat16(h);
    Wl[i] = __float2bfloat16(l);
}

// ------------------------- column stats over bf16 hi/lo ---------------------
__global__ void stats_partial_bf(const bf16* __restrict__ Hh, const bf16* __restrict__ Hl,
                                 float* __restrict__ ps, float* __restrict__ pss)
{
    int col = threadIdx.x;                     // 512
    size_t base = (size_t)blockIdx.x * 256 * 512 + col;
    float s = 0.f, ss = 0.f;
    #pragma unroll 4
    for (int r = 0; r < 256; ++r) {
        size_t idx = base + (size_t)r * 512;
        float v = __bfloat162float(Hh[idx]) + __bfloat162float(Hl[idx]);
        s += v; ss = fmaf(v, v, ss);
    }
    ps [blockIdx.x * 512 + col] = s;
    pss[blockIdx.x * 512 + col] = ss;
}

__global__ void stats_final(const float* __restrict__ ps, const float* __restrict__ pss,
                            const float* __restrict__ g,  const float* __restrict__ bt,
                            float* __restrict__ scale, float* __restrict__ shift)
{
    int col = threadIdx.x;
    float s = 0.f, ss = 0.f;
    for (int b = 0; b < 256; ++b) {
        s  += ps [b * 512 + col];
        ss += pss[b * 512 + col];
    }
    float mean = s * (1.0f / 65536.0f);
    float var  = fmaf(-mean, mean, ss * (1.0f / 65536.0f));
    float sc   = g[col] * rsqrtf(var + 1e-5f);
    scale[col] = sc;
    shift[col] = fmaf(-mean, sc, bt[col]);
}

// ------------------------- bias fold ----------------------------------------
__global__ void fold_bias(const float* __restrict__ Wm, const float* __restrict__ b,
                          const float* __restrict__ vec, float* __restrict__ out, int K)
{
    int j = blockIdx.x;
    float s = 0.f;
    for (int k = threadIdx.x; k < K; k += blockDim.x)
        s = fmaf(Wm[(size_t)j * K + k], vec[k], s);
    #pragma unroll
    for (int o = 16; o; o >>= 1) s += __shfl_xor_sync(0xffffffffu, s, o);
    __shared__ float red[4];
    if ((threadIdx.x & 31) == 0) red[threadIdx.x >> 5] = s;
    __syncthreads();
    if (threadIdx.x == 0) out[j] = b[j] + red[0] + red[1] + red[2] + red[3];
}

// ------------------------- row L2 normalize on hi/lo ------------------------
__global__ void rownorm_bf(bf16* __restrict__ Yh, bf16* __restrict__ Yl)
{
    int wid = threadIdx.x >> 5, lane = threadIdx.x & 31;  // 8 warps
    size_t row = (size_t)blockIdx.x * 8 + wid;
    uint4* ph = reinterpret_cast<uint4*>(Yh + row * CU_N); // 32 uint4 / row
    uint4* pl = reinterpret_cast<uint4*>(Yl + row * CU_N);
    uint4 uh = ph[lane], ul = pl[lane];
    uint32_t hw[4] = {uh.x, uh.y, uh.z, uh.w};
    uint32_t lw[4] = {ul.x, ul.y, ul.z, ul.w};
    float v[8];
    #pragma unroll
    for (int q = 0; q < 4; ++q) {
        float2 a = bf2_to_f2(hw[q]);
        float2 b = bf2_to_f2(lw[q]);
        v[2*q]   = a.x + b.x;
        v[2*q+1] = a.y + b.y;
    }
    float ss = 0.f;
    #pragma unroll
    for (int q = 0; q < 8; ++q) ss = fmaf(v[q], v[q], ss);
    #pragma unroll
    for (int o = 16; o; o >>= 1) ss += __shfl_xor_sync(0xffffffffu, ss, o);
    float s = 16.0f * rsqrtf(ss);
    float h[8], l[8];
    #pragma unroll
    for (int q = 0; q < 8; ++q) split1(s * v[q], h[q], l[q]);
    uh = make_uint4(f2_to_bf2(h[0],h[1]), f2_to_bf2(h[2],h[3]),
                    f2_to_bf2(h[4],h[5]), f2_to_bf2(h[6],h[7]));
    ul = make_uint4(f2_to_bf2(l[0],l[1]), f2_to_bf2(l[2],l[3]),
                    f2_to_bf2(l[4],l[5]), f2_to_bf2(l[6],l[7]));
    ph[lane] = uh;
    pl[lane] = ul;
}

// ------------------------- tcgen05 GEMM -------------------------------------
// D[128 x 256] tile. C = act( (Ah+Al)[M,K] @ ((Wh+Wl)[N,K])^T + bias )
// 3-term bf16 emulation: Ah*Wh + Ah*Wl + Al*Wh, fp32 accum in TMEM.
#define STAGE_BYTES  (96*1024)
#define SMEM_TOTAL_G (1024 + 2*STAGE_BYTES)
#define EPI_LD 264

template<int K, bool PRELU, bool SPLIT_OUT>
__global__ void __launch_bounds__(256, 1)
tc_gemm(const bf16* __restrict__ Ah, const bf16* __restrict__ Al,
        const bf16* __restrict__ Wh, const bf16* __restrict__ Wl,
        const float* __restrict__ bias, const float* __restrict__ aprelu,
        bf16* __restrict__ Oh, bf16* __restrict__ Ol, float* __restrict__ Of,
        int ldo)
{
#if TC_OK
    constexpr int NK = K / 64;
    constexpr uint32_t IDESC =
        (1u << 4) | (1u << 7) | (1u << 10) |        // F32 accum, BF16 a/b
        ((256u / 8) << 17) | ((128u / 16) << 24);   // N=256, M=128
    extern __shared__ __align__(1024) char sm[];
    const uint32_t sbase = smem_u32(sm);
    const int tid = threadIdx.x, wid = tid >> 5, lane = tid & 31;
    const size_t m0 = (size_t)blockIdx.y * 128;
    const size_t n0 = (size_t)blockIdx.x * 256;

    if (wid == 0) TCGEN05_ALLOC(sbase + 0, 256);
    if (tid == 0) { MBARRIER_INIT(sbase + 16, 1); MBARRIER_INIT(sbase + 24, 1); }
    FENCE_PROXY_ASYNC();
    __syncthreads();
    uint32_t tmem;
    asm volatile("ld.shared.b32 %0, [%1];" : "=r"(tmem) : "r"(sbase + 0));

    int ph0 = 0, ph1 = 0;
    #pragma unroll 1
    for (int kc = 0; kc < NK; ++kc) {
        const int s = kc & 1;
        char* stp = sm + 1024 + s * STAGE_BYTES;
        const uint32_t stb = sbase + 1024 + s * STAGE_BYTES;
        if (kc >= 2) {
            if (s == 0) { MBARRIER_WAIT_PARITY(sbase + 16, ph0); ph0 ^= 1; }
            else        { MBARRIER_WAIT_PARITY(sbase + 24, ph1); ph1 ^= 1; }
        }
        // A tiles: 128 rows x 64 bf16 (128B rows, SW128); hi then lo
        #pragma unroll
        for (int i = 0; i < 4; ++i) {
            int idx = tid + i * 256;
            int r = idx >> 3, c = idx & 7;
            size_t g = (m0 + r) * (size_t)K + (size_t)kc * 64 + c * 8;
            uint32_t b = r * 128 + c * 16;
            uint32_t sw = b ^ ((b >> 3) & 0x70);
            *reinterpret_cast<uint4*>(stp + sw)         = *reinterpret_cast<const uint4*>(Ah + g);
            *reinterpret_cast<uint4*>(stp + 16384 + sw) = *reinterpret_cast<const uint4*>(Al + g);
        }
        // W tiles: 256 rows x 64 bf16; hi then lo
        #pragma unroll
        for (int i = 0; i < 8; ++i) {
            int idx = tid + i * 256;
            int r = idx >> 3, c = idx & 7;
            size_t g = (n0 + r) * (size_t)K + (size_t)kc * 64 + c * 8;
            uint32_t b = r * 128 + c * 16;
            uint32_t sw = b ^ ((b >> 3) & 0x70);
            *reinterpret_cast<uint4*>(stp + 32768 + sw) = *reinterpret_cast<const uint4*>(Wh + g);
            *reinterpret_cast<uint4*>(stp + 65536 + sw) = *reinterpret_cast<const uint4*>(Wl + g);
        }
        FENCE_PROXY_ASYNC();
        __syncthreads();
        if (wid == 0 && elect1()) {
            uint64_t dAh = make_desc_sw128(stb);
            uint64_t dAl = make_desc_sw128(stb + 16384);
            uint64_t dWh = make_desc_sw128(stb + 32768);
            uint64_t dWl = make_desc_sw128(stb + 65536);
            #pragma unroll
            for (int ks = 0; ks < 4; ++ks) {
                mma_f16_ss(tmem, dAh + ks*2, dWh + ks*2, IDESC, (kc == 0 && ks == 0) ? 0u : 1u);
                mma_f16_ss(tmem, dAh + ks*2, dWl + ks*2, IDESC, 1u);
                mma_f16_ss(tmem, dAl + ks*2, dWh + ks*2, IDESC, 1u);
            }
            TCGEN05_COMMIT(sbase + 16 + s * 8);
        }
    }
    // wait for the last commit (covers all outstanding MMAs)
    {
        const int s = (NK - 1) & 1;
        if (s == 0) { MBARRIER_WAIT_PARITY(sbase + 16, ph0); }
        else        { MBARRIER_WAIT_PARITY(sbase + 24, ph1); }
    }
    TCGEN05_FENCE_AFTER();

    // epilogue: LDTM -> bias (+prelu) -> (split hi/lo | f32) via SMEM transpose
    const float alpha = PRELU ? *aprelu : 0.f;
    const int rloc = (wid & 3) * 32 + lane;
    const int cb = (wid >> 2) * 128;
    bf16*  smH = reinterpret_cast<bf16*>(sm + 1024);
    bf16*  smL = smH + 128 * EPI_LD;
    float* smF = reinterpret_cast<float*>(sm + 1024);

    #pragma unroll 1
    for (int ch = 0; ch < 4; ++ch) {
        int c0 = cb + ch * 32;
        uint32_t r[32];
        TCGEN05_LD_32X32B_X32(r, tmem + c0);
        TCGEN05_WAIT_LD();
        #pragma unroll
        for (int j = 0; j < 32; ++j) {
            float o = __uint_as_float(r[j]) + bias[n0 + c0 + j];
            if (PRELU) o = (o > 0.f) ? o : alpha * o;
            if (SPLIT_OUT) {
                float h, l;
                split1(o, h, l);
                smH[rloc * EPI_LD + c0 + j] = __float2bfloat16(h);
                smL[rloc * EPI_LD + c0 + j] = __float2bfloat16(l);
            } else {
                smF[rloc * EPI_LD + c0 + j] = o;
            }
        }
    }
    TCGEN05_FENCE_BEFORE();
    __syncthreads();
    if (wid == 0) { TCGEN05_RELINQUISH(); TCGEN05_DEALLOC(tmem, 256); }

    if (SPLIT_OUT) {
        // 128 rows x 256 cols bf16 = 4096 uint4 per tensor, 32 uint4 per row
        #pragma unroll
        for (int i = 0; i < 16; ++i) {
            int idx = tid + i * 256;
            int r = idx >> 5, c = idx & 31;
            size_t g = (m0 + r) * (size_t)ldo + n0 + c * 8;
            *reinterpret_cast<uint4*>(Oh + g) =
                *reinterpret_cast<uint4*>(smH + r * EPI_LD + c * 8);
            *reinterpret_cast<uint4*>(Ol + g) =
                *reinterpret_cast<uint4*>(smL + r * EPI_LD + c * 8);
        }
    } else {
        // 128 rows x 256 cols f32 = 8192 uint4, 64 uint4 per row
        #pragma unroll
        for (int i = 0; i < 32; ++i) {
            int idx = tid + i * 256;
            int r = idx >> 6, c = idx & 63;
            size_t g = (m0 + r) * (size_t)ldo + n0 + c * 4;
            *reinterpret_cast<uint4*>(Of + g) =
                *reinterpret_cast<uint4*>(smF + r * EPI_LD + c * 4);
        }
    }
#else
    // --------- correct SIMT fallback (compute_103 virtual pass; not used) ---
    const int tid = threadIdx.x;
    const size_t m0 = (size_t)blockIdx.y * 128;
    const size_t n0 = (size_t)blockIdx.x * 256;
    const float alpha = PRELU ? *aprelu : 0.f;
    for (int o = tid; o < 128 * 256; o += 256) {
        int r = o >> 8, c = o & 255;
        float acc = 0.f;
        for (int k = 0; k < K; ++k) {
            float a = __bfloat162float(Ah[(m0 + r) * K + k]) +
                      __bfloat162float(Al[(m0 + r) * K + k]);
            float w = __bfloat162float(Wh[(n0 + c) * K + k]) +
                      __bfloat162float(Wl[(n0 + c) * K + k]);
            acc = fmaf(a, w, acc);
        }
        float v = acc + bias[n0 + c];
        if (PRELU) v = (v > 0.f) ? v : alpha * v;
        size_t g = (m0 + r) * (size_t)ldo + n0 + c;
        if (SPLIT_OUT) {
            float h, l;
            split1(v, h, l);
            Oh[g] = __float2bfloat16(h);
            Ol[g] = __float2bfloat16(l);
        } else {
            Of[g] = v;
        }
    }
#endif
}

// ---------------------------------------------------------------------------
extern "C" void kernel_launch(void* const* d_in, const int* in_sizes, int n_in,
                              void* d_out, int out_size)
{
    const float* x    = (const float*)d_in[0];
    const float* noise= (const float*)d_in[1];
    const float* W1   = (const float*)d_in[2];
    const float* b1   = (const float*)d_in[3];
    const float* a1   = (const float*)d_in[4];
    const float* g1v  = (const float*)d_in[5];
    const float* bt1  = (const float*)d_in[6];
    const float* W2   = (const float*)d_in[7];
    const float* b2   = (const float*)d_in[8];
    const float* W3   = (const float*)d_in[9];
    const float* b3   = (const float*)d_in[10];
    const float* a2   = (const float*)d_in[11];
    const float* g2v  = (const float*)d_in[12];
    const float* bt2  = (const float*)d_in[13];
    const float* W4   = (const float*)d_in[14];
    const float* b4   = (const float*)d_in[15];
    const float* fir  = (const float*)d_in[16];
    float* out = (float*)d_out;

    bf16 *xh,*xl,*hh,*hl,*yh,*yl,*dh,*dl;
    bf16 *w1h,*w1l,*w2h,*w2l,*w3h,*w3l,*w4h,*w4l;
    float *ps,*pss,*scale,*shift,*beff,*nc;
    cudaGetSymbolAddress((void**)&xh, g_xh);  cudaGetSymbolAddress((void**)&xl, g_xl);
    cudaGetSymbolAddress((void**)&hh, g_hh);  cudaGetSymbolAddress((void**)&hl, g_hl);
    cudaGetSymbolAddress((void**)&yh, g_yh);  cudaGetSymbolAddress((void**)&yl, g_yl);
    cudaGetSymbolAddress((void**)&dh, g_dh);  cudaGetSymbolAddress((void**)&dl, g_dl);
    cudaGetSymbolAddress((void**)&w1h, g_W1h); cudaGetSymbolAddress((void**)&w1l, g_W1l);
    cudaGetSymbolAddress((void**)&w2h, g_W2h); cudaGetSymbolAddress((void**)&w2l, g_W2l);
    cudaGetSymbolAddress((void**)&w3h, g_W3h); cudaGetSymbolAddress((void**)&w3l, g_W3l);
    cudaGetSymbolAddress((void**)&w4h, g_W4h); cudaGetSymbolAddress((void**)&w4l, g_W4l);
    cudaGetSymbolAddress((void**)&ps, g_ps);   cudaGetSymbolAddress((void**)&pss, g_pss);
    cudaGetSymbolAddress((void**)&scale, g_scale); cudaGetSymbolAddress((void**)&shift, g_shift);
    cudaGetSymbolAddress((void**)&beff, g_beff);   cudaGetSymbolAddress((void**)&nc, g_nc);

    cudaFuncSetAttribute(tc_gemm<512, true,  true >, cudaFuncAttributeMaxDynamicSharedMemorySize, SMEM_TOTAL_G);
    cudaFuncSetAttribute(tc_gemm<512, false, true >, cudaFuncAttributeMaxDynamicSharedMemorySize, SMEM_TOTAL_G);
    cudaFuncSetAttribute(tc_gemm<256, true,  true >, cudaFuncAttributeMaxDynamicSharedMemorySize, SMEM_TOTAL_G);
    cudaFuncSetAttribute(tc_gemm<512, false, false>, cudaFuncAttributeMaxDynamicSharedMemorySize, SMEM_TOTAL_G);

    // 1) noise FIR (also writes noise_clipped to output tail)
    conv_noise<<<1, 256>>>(noise, fir, nc, out + (size_t)B_SZ * BLK);

    // 2) split x and W1
    split_f32<<<(B_SZ * (size_t)BLK) / 8 / 256, 256>>>(x, xh, xl);
    split_w<<<512 * 512 / 256, 256>>>(W1, nullptr, w1h, w1l, 511);

    // 3) h = prelu(x @ W1^T + b1)  -> hi/lo
    tc_gemm<512, true, true><<<dim3(2, 512), 256, SMEM_TOTAL_G>>>(
        xh, xl, w1h, w1l, b1, a1, hh, hl, nullptr, 512);

    // 4) BN1 stats
    stats_partial_bf<<<256, 512>>>(hh, hl, ps, pss);
    stats_final<<<1, 512>>>(ps, pss, g1v, bt1, scale, shift);

    // 5) y = h @ (W2*scale)^T + (b2 + W2@shift)
    fold_bias<<<CU_N, 128>>>(W2, b2, shift, beff, 512);
    split_w<<<256 * 512 / 256, 256>>>(W2, scale, w2h, w2l, 511);
    tc_gemm<512, false, true><<<dim3(1, 512), 256, SMEM_TOTAL_G>>>(
        hh, hl, w2h, w2l, beff, nullptr, yh, yl, nullptr, 256);

    // 6) row L2 normalize y
    rownorm_bf<<<B_SZ / 8, 256>>>(yh, yl);

    // 7) d = prelu(y @ W3^T + (b3 + W3@nc))
    fold_bias<<<BLK, 128>>>(W3, b3, nc, beff, 256);
    split_w<<<512 * 256 / 256, 256>>>(W3, nullptr, w3h, w3l, 255);
    tc_gemm<256, true, true><<<dim3(2, 512), 256, SMEM_TOTAL_G>>>(
        yh, yl, w3h, w3l, beff, a2, dh, dl, nullptr, 512);

    // 8) BN2 stats
    stats_partial_bf<<<256, 512>>>(dh, dl, ps, pss);
    stats_final<<<1, 512>>>(ps, pss, g2v, bt2, scale, shift);

    // 9) out = d @ (W4*scale)^T + (b4 + W4@shift)   (fp32)
    fold_bias<<<BLK, 128>>>(W4, b4, shift, beff, 512);
    split_w<<<512 * 512 / 256, 256>>>(W4, scale, w4h, w4l, 511);
    tc_gemm<512, false, false><<<dim3(2, 512), 256, SMEM_TOTAL_G>>>(
        dh, dl, w4h, w4l, beff, nullptr, nullptr, nullptr, out, 512);
}